// round 6
// baseline (speedup 1.0000x reference)
#include <cuda_runtime.h>
#include <cstdint>

// mean_aggregator: out[b,:] = (1/32) * sum_s emb[neighbors[b,s], :]
// B=50000, S=32, D=128, emb 500000x128 fp32 (256 MB > 126 MB L2).
//
// Persistent one-wave kernel. Each warp owns ROWS rows; ids warp-bitonic
// sorted into smem once; float4 accumulators live in registers for the whole
// kernel. The table id space is swept in NW fixed 64 MB windows; a soft grid
// barrier (pure locality fence — correctness never depends on it) keeps all
// resident warps in the same window so each unique table row is fetched from
// DRAM ~once. No multi-pass output RMW, no index re-reads.

#define THREADS 256
#define WPB (THREADS / 32)
#define ROWS 11
#define NW 4
#define SPIN_LIMIT (1u << 17)

__device__ unsigned g_bar[NW];   // NW-1 barrier counters + 1 exit counter (zero-init)

__device__ __forceinline__ void grid_fence(int b, int nblocks)
{
    __syncthreads();
    if (threadIdx.x == 0) {
        const unsigned old = atomicAdd(&g_bar[b], 1u);
        if (old == (unsigned)(nblocks - 1) && b > 0)
            g_bar[b - 1] = 0;                       // safe: all passed spin b-1
        unsigned tries = 0;
        while (*(volatile unsigned*)&g_bar[b] < (unsigned)nblocks &&
               tries < SPIN_LIMIT) {
            ++tries;
            __nanosleep(64);
        }
    }
    __syncthreads();
}

__global__ __launch_bounds__(THREADS, 4)
void mean_agg_persistent(const int* __restrict__ neighbors,
                         const float4* __restrict__ emb,   // [N, 32] float4
                         float4* __restrict__ out,         // [B, 32] float4
                         int batch, int num_nodes)
{
    __shared__ int           s_ids[WPB][ROWS][32];
    __shared__ unsigned char s_bnd[WPB][ROWS][NW + 1];

    const int wid  = threadIdx.x >> 5;
    const int lane = threadIdx.x & 31;
    const int nblocks = gridDim.x;
    const int W    = nblocks * WPB;           // total warps
    const int gw   = blockIdx.x * WPB + wid;  // this warp's id

    // ---- load + sort ids, compute window boundaries ----
    #pragma unroll
    for (int r = 0; r < ROWS; ++r) {
        const int row = gw + r * W;
        int v = (row < batch) ? neighbors[row * 32 + lane] : 0x7fffffff;

        // 32-element warp-bitonic sort (ascending)
        #pragma unroll
        for (int k = 2; k <= 32; k <<= 1) {
            #pragma unroll
            for (int j = k >> 1; j > 0; j >>= 1) {
                const int other  = __shfl_xor_sync(0xffffffffu, v, j);
                const bool up    = ((lane & k) == 0);
                const bool lower = ((lane & j) == 0);
                v = ((lower == up) ? min(v, other) : max(v, other));
            }
        }
        s_ids[wid][r][lane] = v;

        // boundary[w] = count of ids < lo_w  (sentinel 0x7fffffff excluded
        // automatically because lo_NW = num_nodes)
        #pragma unroll
        for (int w = 0; w <= NW; ++w) {
            const int lo = (int)(((long long)num_nodes * w) / NW);
            const unsigned m = __ballot_sync(0xffffffffu, v < lo);
            if (lane == 0) s_bnd[wid][r][w] = (unsigned char)__popc(m);
        }
    }
    __syncthreads();

    // ---- register-resident accumulators ----
    float4 acc[ROWS];
    #pragma unroll
    for (int r = 0; r < ROWS; ++r)
        acc[r] = make_float4(0.f, 0.f, 0.f, 0.f);

    // ---- windowed gather sweep ----
    for (int w = 0; w < NW; ++w) {
        #pragma unroll
        for (int r = 0; r < ROWS; ++r) {
            int i = s_bnd[wid][r][w];
            const int e = s_bnd[wid][r][w + 1];
            for (; i < e; ++i) {
                const int n = s_ids[wid][r][i];        // uniform LDS
                const float4 v = __ldg(&emb[(size_t)n * 32 + lane]);
                acc[r].x += v.x;
                acc[r].y += v.y;
                acc[r].z += v.z;
                acc[r].w += v.w;
            }
        }
        if (w < NW - 1) grid_fence(w, nblocks);
    }

    // ---- write means ----
    const float inv = 1.0f / 32.0f;
    #pragma unroll
    for (int r = 0; r < ROWS; ++r) {
        const int row = gw + r * W;
        if (row < batch) {
            float4 a = acc[r];
            a.x *= inv; a.y *= inv; a.z *= inv; a.w *= inv;
            out[(size_t)row * 32 + lane] = a;
        }
    }

    // ---- exit counter: reset barrier state for the next graph replay ----
    __syncthreads();
    if (threadIdx.x == 0) {
        const unsigned old = atomicAdd(&g_bar[NW - 1], 1u);
        if (old == (unsigned)(nblocks - 1)) {
            g_bar[NW - 2] = 0;
            g_bar[NW - 1] = 0;
        }
    }
}

// Fallback (R1 kernel) for unexpected shapes that exceed persistent capacity.
__global__ __launch_bounds__(THREADS)
void mean_agg_naive(const int* __restrict__ neighbors,
                    const float4* __restrict__ emb,
                    float4* __restrict__ out, int batch)
{
    const int warp = (blockIdx.x * blockDim.x + threadIdx.x) >> 5;
    const int lane = threadIdx.x & 31;
    if (warp >= batch) return;
    const int my = neighbors[warp * 32 + lane];
    float4 acc = make_float4(0.f, 0.f, 0.f, 0.f);
    #pragma unroll
    for (int s = 0; s < 32; ++s) {
        const int n = __shfl_sync(0xffffffffu, my, s);
        const float4 v = __ldg(&emb[(size_t)n * 32 + lane]);
        acc.x += v.x; acc.y += v.y; acc.z += v.z; acc.w += v.w;
    }
    const float inv = 1.0f / 32.0f;
    acc.x *= inv; acc.y *= inv; acc.z *= inv; acc.w *= inv;
    out[(size_t)warp * 32 + lane] = acc;
}

extern "C" void kernel_launch(void* const* d_in, const int* in_sizes, int n_in,
                              void* d_out, int out_size)
{
    const int* neighbors = (const int*)d_in[0];     // [B, 32] int32
    const float4* emb    = (const float4*)d_in[1];  // [N, 128] fp32 as float4

    const int batch     = in_sizes[0] / 32;         // 50000
    const int num_nodes = in_sizes[1] / 128;        // 500000

    int sms = 0;
    if (cudaDeviceGetAttribute(&sms, cudaDevAttrMultiProcessorCount, 0) !=
            cudaSuccess || sms <= 0)
        sms = 148;

    const int nblocks = sms * 4;                    // one guaranteed wave
    const long long capacity = (long long)nblocks * WPB * ROWS;

    if ((long long)batch <= capacity) {
        mean_agg_persistent<<<nblocks, THREADS>>>(neighbors, emb,
                                                  (float4*)d_out,
                                                  batch, num_nodes);
    } else {
        const int blocks = (batch + WPB - 1) / WPB;
        mean_agg_naive<<<blocks, THREADS>>>(neighbors, emb,
                                            (float4*)d_out, batch);
    }
}

// round 7
// speedup vs baseline: 1.5308x; 1.5308x over previous
#include <cuda_runtime.h>
#include <cstdint>

// mean_aggregator: out[b,:] = (1/32) * sum_s emb[neighbors[b,s], :]
// B=50000, S=32, D=128, emb 500000x128 fp32 (256 MB > 126 MB L2).
//
// Persistent one-wave kernel, position-windowed sorted gather:
//  - each warp owns ROWS rows; ids warp-bitonic sorted once into smem
//  - float4 accumulators stay in registers for the whole kernel
//  - window w gathers sorted POSITIONS [8w, 8w+8): static trip count ->
//    88 fully unrolled independent loads per warp per window (max MLP)
//  - sorted order makes position ~ value (order statistics), and a soft grid
//    fence between windows keeps every resident warp in the same ~64-100 MB
//    value region -> L2-resident window, each table row ~one DRAM fetch.
//  - fence is a pure locality hint: correctness never depends on it
//    (bounded spin, self-resetting for graph replay).

#define THREADS 256
#define WPB (THREADS / 32)
#define ROWS 11
#define NW 4                       // 4 windows x 8 positions
#define POS_PER_W (32 / NW)
#define SPIN_LIMIT (1u << 17)

__device__ unsigned g_bar[NW];     // NW-1 fence counters + 1 exit counter

__device__ __forceinline__ void grid_fence(int b, int nblocks)
{
    __syncthreads();
    if (threadIdx.x == 0) {
        const unsigned old = atomicAdd(&g_bar[b], 1u);
        if (old == (unsigned)(nblocks - 1) && b > 0)
            g_bar[b - 1] = 0;                  // all blocks passed fence b-1
        unsigned tries = 0;
        while (*(volatile unsigned*)&g_bar[b] < (unsigned)nblocks &&
               tries < SPIN_LIMIT) {
            ++tries;
            __nanosleep(64);
        }
    }
    __syncthreads();
}

__global__ __launch_bounds__(THREADS, 4)
void mean_agg_poswin(const int* __restrict__ neighbors,
                     const float4* __restrict__ emb,   // [N, 32] float4
                     float4* __restrict__ out,         // [B, 32] float4
                     int batch)
{
    __shared__ int s_ids[WPB][ROWS][32];

    const int wid  = threadIdx.x >> 5;
    const int lane = threadIdx.x & 31;
    const int nblocks = gridDim.x;
    const int W   = nblocks * WPB;
    const int gw  = blockIdx.x * WPB + wid;

    // ---- load + warp-bitonic sort each owned row's 32 ids ----
    #pragma unroll
    for (int r = 0; r < ROWS; ++r) {
        const int row = gw + r * W;
        // Sentinel id 0 for inactive rows: harmless extra loads, result unused.
        int v = (row < batch) ? neighbors[row * 32 + lane] : 0;

        #pragma unroll
        for (int k = 2; k <= 32; k <<= 1) {
            #pragma unroll
            for (int j = k >> 1; j > 0; j >>= 1) {
                const int other  = __shfl_xor_sync(0xffffffffu, v, j);
                const bool up    = ((lane & k) == 0);
                const bool lower = ((lane & j) == 0);
                v = ((lower == up) ? min(v, other) : max(v, other));
            }
        }
        s_ids[wid][r][lane] = v;
    }
    __syncthreads();

    float4 acc[ROWS];
    #pragma unroll
    for (int r = 0; r < ROWS; ++r)
        acc[r] = make_float4(0.f, 0.f, 0.f, 0.f);

    // ---- position-windowed gather: static, fully unrolled ----
    for (int w = 0; w < NW; ++w) {
        const int base = w * POS_PER_W;
        #pragma unroll
        for (int r = 0; r < ROWS; ++r) {
            #pragma unroll
            for (int p = 0; p < POS_PER_W; ++p) {
                const int n = s_ids[wid][r][base + p];     // LDS broadcast
                const float4 v = __ldg(&emb[(size_t)n * 32 + lane]);
                acc[r].x += v.x;
                acc[r].y += v.y;
                acc[r].z += v.z;
                acc[r].w += v.w;
            }
        }
        if (w < NW - 1) grid_fence(w, nblocks);
    }

    // ---- write means ----
    const float inv = 1.0f / 32.0f;
    #pragma unroll
    for (int r = 0; r < ROWS; ++r) {
        const int row = gw + r * W;
        if (row < batch) {
            float4 a = acc[r];
            a.x *= inv; a.y *= inv; a.z *= inv; a.w *= inv;
            out[(size_t)row * 32 + lane] = a;
        }
    }

    // ---- exit: reset fence state for next graph replay ----
    __syncthreads();
    if (threadIdx.x == 0) {
        const unsigned old = atomicAdd(&g_bar[NW - 1], 1u);
        if (old == (unsigned)(nblocks - 1)) {
            g_bar[NW - 2] = 0;
            g_bar[NW - 1] = 0;
        }
    }
}

// Fallback (R1 kernel) for shapes exceeding persistent capacity.
__global__ __launch_bounds__(THREADS)
void mean_agg_naive(const int* __restrict__ neighbors,
                    const float4* __restrict__ emb,
                    float4* __restrict__ out, int batch)
{
    const int warp = (blockIdx.x * blockDim.x + threadIdx.x) >> 5;
    const int lane = threadIdx.x & 31;
    if (warp >= batch) return;
    const int my = neighbors[warp * 32 + lane];
    float4 acc = make_float4(0.f, 0.f, 0.f, 0.f);
    #pragma unroll
    for (int s = 0; s < 32; ++s) {
        const int n = __shfl_sync(0xffffffffu, my, s);
        const float4 v = __ldg(&emb[(size_t)n * 32 + lane]);
        acc.x += v.x; acc.y += v.y; acc.z += v.z; acc.w += v.w;
    }
    const float inv = 1.0f / 32.0f;
    acc.x *= inv; acc.y *= inv; acc.z *= inv; acc.w *= inv;
    out[(size_t)warp * 32 + lane] = acc;
}

extern "C" void kernel_launch(void* const* d_in, const int* in_sizes, int n_in,
                              void* d_out, int out_size)
{
    const int* neighbors = (const int*)d_in[0];     // [B, 32] int32
    const float4* emb    = (const float4*)d_in[1];  // [N, 128] fp32 as float4

    const int batch = in_sizes[0] / 32;             // 50000

    int sms = 0;
    if (cudaDeviceGetAttribute(&sms, cudaDevAttrMultiProcessorCount, 0) !=
            cudaSuccess || sms <= 0)
        sms = 148;

    const int nblocks = sms * 4;                    // one guaranteed wave
    const long long capacity = (long long)nblocks * WPB * ROWS;

    if ((long long)batch <= capacity) {
        mean_agg_poswin<<<nblocks, THREADS>>>(neighbors, emb,
                                              (float4*)d_out, batch);
    } else {
        const int blocks = (batch + WPB - 1) / WPB;
        mean_agg_naive<<<blocks, THREADS>>>(neighbors, emb,
                                            (float4*)d_out, batch);
    }
}